// round 1
// baseline (speedup 1.0000x reference)
#include <cuda_runtime.h>

// OpticalDepth: 76 MLPs (2 -> 64 -> 64 -> 1) + sparse channel combine.
// Kernel A: per-net MLP with W2 in shared, f32x2 packed FMA, 2 batch elems/thread.
// Kernel B: channel combination with compile-time index lists + lw/iw branches.

#define NNETS 76
#define HD    64
#define BMAX  32768

// Scratch for tau_all[n][b] = relu(mlp_n(t_p_b)) * composition[gas(n)][b]
__device__ float g_tau[NNETS * BMAX];

typedef unsigned long long ull;

__device__ __forceinline__ ull pk2(float lo, float hi) {
    ull r;
    asm("mov.b64 %0, {%1, %2};" : "=l"(r) : "f"(lo), "f"(hi));
    return r;
}
__device__ __forceinline__ void up2(ull v, float& lo, float& hi) {
    asm("mov.b64 {%0, %1}, %2;" : "=f"(lo), "=f"(hi) : "l"(v));
}
__device__ __forceinline__ ull fma2(ull a, ull b, ull c) {
    ull d;
    asm("fma.rn.f32x2 %0, %1, %2, %3;" : "=l"(d) : "l"(a), "l"(b), "l"(c));
    return d;
}

// ---------------------------------------------------------------------------
// Kernel A: one block = (net n, 256-batch tile). 128 threads, 2 elems/thread.
// ---------------------------------------------------------------------------
__global__ void __launch_bounds__(128, 2)
mlp_kernel(const float* __restrict__ t_p,
           const float* __restrict__ comp,
           const float* __restrict__ W1, const float* __restrict__ b1,
           const float* __restrict__ W2, const float* __restrict__ b2,
           const float* __restrict__ W3, const float* __restrict__ b3,
           int B)
{
    __shared__ float sW2[HD * HD];     // [k][j], j contiguous
    __shared__ float sW1[2 * HD];
    __shared__ float sB1[HD];
    __shared__ float sB2[HD];
    __shared__ float sW3[HD];
    __shared__ float sB3;

    const int n   = blockIdx.y;
    const int tid = threadIdx.x;

    // Cooperative staging of weights for net n
    {
        const float4* gW2 = reinterpret_cast<const float4*>(W2 + (size_t)n * HD * HD);
        float4* s4 = reinterpret_cast<float4*>(sW2);
        #pragma unroll
        for (int i = 0; i < (HD * HD / 4) / 128; ++i)
            s4[tid + i * 128] = gW2[tid + i * 128];
        if (tid < HD) {
            sW1[tid]      = W1[(size_t)n * 2 * HD + tid];
            sW1[HD + tid] = W1[(size_t)n * 2 * HD + HD + tid];
            sB1[tid]      = b1[(size_t)n * HD + tid];
            sB2[tid]      = b2[(size_t)n * HD + tid];
            sW3[tid]      = W3[(size_t)n * HD + tid];
        }
        if (tid == 0) sB3 = b3[n];
    }
    __syncthreads();

    const int bA = blockIdx.x * 256 + tid;
    const int bB = bA + 128;

    const float2 tA = reinterpret_cast<const float2*>(t_p)[bA];
    const float2 tB = reinterpret_cast<const float2*>(t_p)[bB];

    // Layer 1: h1 = relu(W1^T t_p + b1), fully unrolled -> register arrays
    float h1A[HD], h1B[HD];
    #pragma unroll
    for (int k = 0; k < HD; ++k) {
        const float w0 = sW1[k], w1 = sW1[HD + k], bb = sB1[k];
        h1A[k] = fmaxf(fmaf(tA.x, w0, fmaf(tA.y, w1, bb)), 0.0f);
        h1B[k] = fmaxf(fmaf(tB.x, w0, fmaf(tB.y, w1, bb)), 0.0f);
    }

    // Layers 2+3 fused: process j in 4 tiles of 16 (jt loop NOT unrolled to
    // bound code size; inner k loop fully unrolled so h1 stays in registers).
    float keA = sB3, keB = sB3;
    #pragma unroll 1
    for (int jt = 0; jt < 4; ++jt) {
        const int j0 = jt * 16;
        ull accA[8], accB[8];
        #pragma unroll
        for (int p = 0; p < 8; ++p) {
            const ull bv = pk2(sB2[j0 + 2 * p], sB2[j0 + 2 * p + 1]);
            accA[p] = bv;
            accB[p] = bv;
        }
        #pragma unroll
        for (int k = 0; k < HD; ++k) {
            const ull ha = pk2(h1A[k], h1A[k]);
            const ull hb = pk2(h1B[k], h1B[k]);
            const ulonglong2* w =
                reinterpret_cast<const ulonglong2*>(&sW2[k * HD + j0]);
            const ulonglong2 q0 = w[0], q1 = w[1], q2 = w[2], q3 = w[3];
            accA[0] = fma2(ha, q0.x, accA[0]);  accB[0] = fma2(hb, q0.x, accB[0]);
            accA[1] = fma2(ha, q0.y, accA[1]);  accB[1] = fma2(hb, q0.y, accB[1]);
            accA[2] = fma2(ha, q1.x, accA[2]);  accB[2] = fma2(hb, q1.x, accB[2]);
            accA[3] = fma2(ha, q1.y, accA[3]);  accB[3] = fma2(hb, q1.y, accB[3]);
            accA[4] = fma2(ha, q2.x, accA[4]);  accB[4] = fma2(hb, q2.x, accB[4]);
            accA[5] = fma2(ha, q2.y, accA[5]);  accB[5] = fma2(hb, q2.y, accB[5]);
            accA[6] = fma2(ha, q3.x, accA[6]);  accB[6] = fma2(hb, q3.x, accB[6]);
            accA[7] = fma2(ha, q3.y, accA[7]);  accB[7] = fma2(hb, q3.y, accB[7]);
        }
        // relu + layer 3 dot with W3
        #pragma unroll
        for (int p = 0; p < 8; ++p) {
            const float w3lo = sW3[j0 + 2 * p], w3hi = sW3[j0 + 2 * p + 1];
            float lo, hi;
            up2(accA[p], lo, hi);
            keA = fmaf(fmaxf(lo, 0.0f), w3lo, keA);
            keA = fmaf(fmaxf(hi, 0.0f), w3hi, keA);
            up2(accB[p], lo, hi);
            keB = fmaf(fmaxf(lo, 0.0f), w3lo, keB);
            keB = fmaf(fmaxf(hi, 0.0f), w3hi, keB);
        }
    }
    keA = fmaxf(keA, 0.0f);
    keB = fmaxf(keB, 0.0f);

    // gas id: h2o<29, o3<42, co2<51, n2o<54, ch4<63, else u
    const int g = (n < 29) ? 0 : (n < 42) ? 1 : (n < 51) ? 2
                : (n < 54) ? 3 : (n < 63) ? 4 : 5;
    const float* cg = comp + (size_t)g * B;
    g_tau[(size_t)n * B + bA] = keA * cg[bA];
    g_tau[(size_t)n * B + bB] = keB * cg[bB];
}

// ---------------------------------------------------------------------------
// Kernel B: channel combination (compile-time index lists) + lw/iw branches.
// out layout: [0,30B) tau_gases, [30B,60B) tau_lw, [60B,90B) tau_iw
// ---------------------------------------------------------------------------
__global__ void __launch_bounds__(256)
combine_kernel(const float* __restrict__ comp,
               const float* __restrict__ null_lw, const float* __restrict__ null_iw,
               const float* __restrict__ W_lw, const float* __restrict__ b_lw,
               const float* __restrict__ W_iw, const float* __restrict__ b_iw,
               float* __restrict__ out, int B)
{
    const int b = blockIdx.x * blockDim.x + threadIdx.x;
    if (b >= B) return;

    float tv[NNETS];
    #pragma unroll
    for (int nn = 0; nn < NNETS; ++nn)
        tv[nn] = g_tau[(size_t)nn * B + b];

    float* outG = out;
    float* outL = out + (size_t)30 * B;
    float* outI = out + (size_t)60 * B;

    float ch[30];
    ch[ 0] = tv[ 0] + tv[29] + tv[42] + tv[51] + tv[54] + tv[63];
    ch[ 1] = tv[ 0] + tv[29] + tv[42] + tv[51] + tv[54] + tv[63];
    ch[ 2] = tv[ 1] + tv[30] + tv[43] + tv[52] + tv[55] + tv[64];
    ch[ 3] = tv[ 2] + tv[31] + tv[44] + tv[53] + tv[56] + tv[65];
    ch[ 4] = tv[ 3] + tv[57];
    ch[ 5] = tv[ 4] + tv[58];
    ch[ 6] = tv[ 5] + tv[45];
    ch[ 7] = tv[ 6] + tv[46];
    ch[ 8] = tv[ 7] + tv[59];
    ch[ 9] = tv[ 8] + tv[60];
    ch[10] = tv[ 9] + tv[47];
    ch[11] = tv[10] + tv[48];
    ch[12] = tv[11] + tv[61];
    ch[13] = tv[12] + tv[62];
    ch[14] = tv[13] + tv[49];
    ch[15] = tv[14] + tv[50];
    ch[16] = tv[15] + tv[66];
    ch[17] = tv[16] + tv[67];
    ch[18] = tv[17] + tv[32] + tv[68];
    ch[19] = tv[18] + tv[33] + tv[69];
    ch[20] = tv[19] + tv[34] + tv[70];
    ch[21] = tv[20] + tv[35] + tv[71];
    ch[22] = tv[21] + tv[36] + tv[72];
    ch[23] = tv[22] + tv[37] + tv[73];
    ch[24] = tv[23];
    ch[25] = tv[24];
    ch[26] = tv[25] + tv[38];
    ch[27] = tv[26] + tv[39];
    ch[28] = tv[27] + tv[40] + tv[74];
    ch[29] = tv[28] + tv[41] + tv[75];

    #pragma unroll
    for (int c = 0; c < 30; ++c)
        outG[(size_t)c * B + b] = ch[c];

    const float c6 = comp[(size_t)6 * B + b];
    const float c7 = comp[(size_t)7 * B + b];
    const float nl = null_lw[b];
    const float ni = null_iw[b];
    #pragma unroll
    for (int c = 0; c < 30; ++c) {
        outL[(size_t)c * B + b] = fmaxf(fmaf(nl, W_lw[c], b_lw[c]), 0.0f) * c6;
        outI[(size_t)c * B + b] = fmaxf(fmaf(ni, W_iw[c], b_iw[c]), 0.0f) * c7;
    }
}

// ---------------------------------------------------------------------------
extern "C" void kernel_launch(void* const* d_in, const int* in_sizes, int n_in,
                              void* d_out, int out_size)
{
    const float* t_p     = (const float*)d_in[0];
    const float* comp    = (const float*)d_in[1];
    const float* null_lw = (const float*)d_in[2];
    const float* null_iw = (const float*)d_in[3];
    const float* W1      = (const float*)d_in[4];
    const float* b1      = (const float*)d_in[5];
    const float* W2      = (const float*)d_in[6];
    const float* b2      = (const float*)d_in[7];
    const float* W3      = (const float*)d_in[8];
    const float* b3      = (const float*)d_in[9];
    const float* W_lw    = (const float*)d_in[10];
    const float* b_lw    = (const float*)d_in[11];
    const float* W_iw    = (const float*)d_in[12];
    const float* b_iw    = (const float*)d_in[13];

    const int B = in_sizes[0] / 2;   // t_p is [B, 2]

    dim3 gridA(B / 256, NNETS);
    mlp_kernel<<<gridA, 128>>>(t_p, comp, W1, b1, W2, b2, W3, b3, B);

    combine_kernel<<<(B + 255) / 256, 256>>>(comp, null_lw, null_iw,
                                             W_lw, b_lw, W_iw, b_iw,
                                             (float*)d_out, B);
}

// round 4
// speedup vs baseline: 1.8229x; 1.8229x over previous
#include <cuda_runtime.h>
#include <cuda_bf16.h>
#include <cstdint>

#define NNETS 76
#define HD    64

__device__ float g_tau[NNETS * 32768];

// ---------------- helpers ----------------
__device__ __forceinline__ unsigned smem_u32(const void* p) {
    unsigned r;
    asm("{ .reg .u64 t; cvta.to.shared.u64 t, %1; cvt.u32.u64 %0, t; }" : "=r"(r) : "l"(p));
    return r;
}
// pack two f32 -> bf16x2 (hi -> upper 16, lo -> lower 16)
__device__ __forceinline__ unsigned pack_bf16x2(float hi, float lo) {
    unsigned r; asm("cvt.rn.bf16x2.f32 %0, %1, %2;" : "=r"(r) : "f"(hi), "f"(lo)); return r;
}

#define LDSM4(r0, r1, r2, r3, addr)                                           \
    asm volatile("ldmatrix.sync.aligned.m8n8.x4.shared.b16 {%0,%1,%2,%3}, [%4];" \
                 : "=r"(r0), "=r"(r1), "=r"(r2), "=r"(r3) : "r"(addr))

#define MMA(c, a, b0, b1)                                                     \
    asm volatile("mma.sync.aligned.m16n8k16.row.col.f32.bf16.bf16.f32 "       \
                 "{%0,%1,%2,%3},{%4,%5,%6,%7},{%8,%9},{%0,%1,%2,%3};"         \
                 : "+f"((c)[0]), "+f"((c)[1]), "+f"((c)[2]), "+f"((c)[3])     \
                 : "r"((a)[0]), "r"((a)[1]), "r"((a)[2]), "r"((a)[3]),        \
                   "r"(b0), "r"(b1))

// ---------------------------------------------------------------------------
// MLP kernel: persistent CTAs over flattened (net, 128-row-tile) job list.
// 128 threads = 4 warps; each warp owns 32 rows of the tile.
// ---------------------------------------------------------------------------
__global__ void __launch_bounds__(128, 2)
mlp_mma_kernel(const float* __restrict__ t_p, const float* __restrict__ comp,
               const float* __restrict__ W1, const float* __restrict__ b1,
               const float* __restrict__ W2, const float* __restrict__ b2,
               const float* __restrict__ W3, const float* __restrict__ b3,
               int B)
{
    __shared__ __align__(128) unsigned char sW2hi[HD * 128];  // [j][k] bf16, swizzled
    __shared__ __align__(128) unsigned char sW2lo[HD * 128];
    __shared__ __align__(8) float sW1a[HD], sW1b[HD], sB1[HD], sB2[HD], sW3[HD];
    __shared__ float sB3;

    const int tid = threadIdx.x;
    const int w   = tid >> 5;
    const int l   = tid & 31;
    const int g   = l >> 2;     // group id (row within 8)
    const int tig = l & 3;      // thread-in-group (k / n column pairs)

    const unsigned w2hi_u = smem_u32(sW2hi);
    const unsigned w2lo_u = smem_u32(sW2lo);

    const int TPN = B >> 7;                       // tiles per net
    const long long J = (long long)NNETS * TPN;   // total jobs
    const int C  = gridDim.x;
    const int js = (int)((J * blockIdx.x) / C);
    const int je = (int)((J * (blockIdx.x + 1)) / C);

    int curnet = -1;
    const float* cg = nullptr;
    float* taun = nullptr;
    float b3v = 0.f;

    #pragma unroll 1
    for (int job = js; job < je; ++job) {
        const int net  = job / TPN;
        const int tile = job - net * TPN;

        if (net != curnet) {
            __syncthreads();   // all warps done reading previous net's weights
            const float* W2n = W2 + (size_t)net * HD * HD;   // [k][j]
            for (int i = tid; i < HD * HD; i += 128) {
                int k = i >> 6, j = i & 63;
                float v = W2n[i];
                __nv_bfloat16 hb = __float2bfloat16(v);
                __nv_bfloat16 lb = __float2bfloat16(v - __bfloat162float(hb));
                unsigned off = (unsigned)(j * 128) + ((((unsigned)(k >> 3)) ^ (j & 7)) << 4)
                             + ((k & 7) << 1);
                *(__nv_bfloat16*)(sW2hi + off) = hb;
                *(__nv_bfloat16*)(sW2lo + off) = lb;
            }
            const float* W1n = W1 + (size_t)net * 2 * HD;
            if (tid < HD) {
                sW1a[tid] = W1n[tid];
                sW1b[tid] = W1n[HD + tid];
                sB1[tid]  = b1[(size_t)net * HD + tid];
                sB2[tid]  = b2[(size_t)net * HD + tid];
                sW3[tid]  = W3[(size_t)net * HD + tid];
            }
            if (tid == 0) sB3 = b3[net];
            __syncthreads();
            curnet = net;
            const int gi = (net < 29) ? 0 : (net < 42) ? 1 : (net < 51) ? 2
                         : (net < 54) ? 3 : (net < 63) ? 4 : 5;
            cg   = comp + (size_t)gi * B;
            taun = g_tau + (size_t)net * B;
            b3v  = sB3;
        }

        const int tbase = tile * 128;
        const int rloc0 = 32 * w + g;   // local rows: rloc0, +8, +16, +24

        // t_p for my 4 fragment rows
        float2 tp[4];
        #pragma unroll
        for (int i = 0; i < 4; ++i)
            tp[i] = ((const float2*)t_p)[tbase + rloc0 + 8 * i];

        // accumulators init with b2 (c0/c2 at col j0, c1/c3 at col j0+1)
        float acc[2][8][4];
        #pragma unroll
        for (int nb = 0; nb < 8; ++nb) {
            float2 b2v = *(const float2*)&sB2[8 * nb + 2 * tig];
            #pragma unroll
            for (int mb = 0; mb < 2; ++mb) {
                acc[mb][nb][0] = b2v.x; acc[mb][nb][1] = b2v.y;
                acc[mb][nb][2] = b2v.x; acc[mb][nb][3] = b2v.y;
            }
        }

        #pragma unroll 1
        for (int kb = 0; kb < 4; ++kb) {
            // ---- layer 1: my A-fragment elements for this k-block ----
            const int k0 = 16 * kb + 2 * tig;        // and k0+8
            const float2 wa0 = *(const float2*)&sW1a[k0];
            const float2 wa1 = *(const float2*)&sW1a[k0 + 8];
            const float2 wb0 = *(const float2*)&sW1b[k0];
            const float2 wb1 = *(const float2*)&sW1b[k0 + 8];
            const float2 bb0 = *(const float2*)&sB1[k0];
            const float2 bb1 = *(const float2*)&sB1[k0 + 8];

            unsigned Ahi[2][4], Alo[2][4];
            #pragma unroll
            for (int i = 0; i < 4; ++i) {
                const float tx = tp[i].x, ty = tp[i].y;
                float h00 = fmaxf(fmaf(tx, wa0.x, fmaf(ty, wb0.x, bb0.x)), 0.f);
                float h01 = fmaxf(fmaf(tx, wa0.y, fmaf(ty, wb0.y, bb0.y)), 0.f);
                float h10 = fmaxf(fmaf(tx, wa1.x, fmaf(ty, wb1.x, bb1.x)), 0.f);
                float h11 = fmaxf(fmaf(tx, wa1.y, fmaf(ty, wb1.y, bb1.y)), 0.f);
                unsigned hi0 = pack_bf16x2(h01, h00);
                unsigned hi1 = pack_bf16x2(h11, h10);
                float r00 = __uint_as_float(hi0 << 16);
                float r01 = __uint_as_float(hi0 & 0xFFFF0000u);
                float r10 = __uint_as_float(hi1 << 16);
                float r11 = __uint_as_float(hi1 & 0xFFFF0000u);
                unsigned lo0 = pack_bf16x2(h01 - r01, h00 - r00);
                unsigned lo1 = pack_bf16x2(h11 - r11, h10 - r10);
                const int mb = i >> 1, sl = i & 1;
                Ahi[mb][sl]     = hi0;  Ahi[mb][2 + sl] = hi1;
                Alo[mb][sl]     = lo0;  Alo[mb][2 + sl] = lo1;
            }

            // ---- B fragments + mma ----
            const unsigned csel = 2 * kb + (l >> 4);
            #pragma unroll
            for (int np = 0; np < 4; ++np) {
                const unsigned n16 = 16 * np + (((unsigned)(l >> 3) & 1) << 3) + (l & 7);
                const unsigned off = n16 * 128 + ((csel ^ (n16 & 7)) << 4);
                unsigned bh0, bh1, bh2, bh3, bl0, bl1, bl2, bl3;
                LDSM4(bh0, bh1, bh2, bh3, w2hi_u + off);
                LDSM4(bl0, bl1, bl2, bl3, w2lo_u + off);
                #pragma unroll
                for (int mb = 0; mb < 2; ++mb) {
                    MMA(acc[mb][2 * np],     Ahi[mb], bh0, bh2);
                    MMA(acc[mb][2 * np],     Alo[mb], bh0, bh2);
                    MMA(acc[mb][2 * np],     Ahi[mb], bl0, bl2);
                    MMA(acc[mb][2 * np + 1], Ahi[mb], bh1, bh3);
                    MMA(acc[mb][2 * np + 1], Alo[mb], bh1, bh3);
                    MMA(acc[mb][2 * np + 1], Ahi[mb], bl1, bl3);
                }
            }
        }

        // ---- epilogue: relu, W3 dot, quad reduce, tau store ----
        #pragma unroll
        for (int mb = 0; mb < 2; ++mb) {
            float p0 = 0.f, p1 = 0.f;
            #pragma unroll
            for (int nb = 0; nb < 8; ++nb) {
                float2 w3v = *(const float2*)&sW3[8 * nb + 2 * tig];
                p0 = fmaf(fmaxf(acc[mb][nb][0], 0.f), w3v.x, p0);
                p0 = fmaf(fmaxf(acc[mb][nb][1], 0.f), w3v.y, p0);
                p1 = fmaf(fmaxf(acc[mb][nb][2], 0.f), w3v.x, p1);
                p1 = fmaf(fmaxf(acc[mb][nb][3], 0.f), w3v.y, p1);
            }
            p0 += __shfl_xor_sync(0xffffffffu, p0, 1);
            p0 += __shfl_xor_sync(0xffffffffu, p0, 2);
            p1 += __shfl_xor_sync(0xffffffffu, p1, 1);
            p1 += __shfl_xor_sync(0xffffffffu, p1, 2);
            if (tig == 0) {
                const int r0 = tbase + 32 * w + 16 * mb + g;
                const int r1 = r0 + 8;
                taun[r0] = fmaxf(p0 + b3v, 0.f) * cg[r0];
                taun[r1] = fmaxf(p1 + b3v, 0.f) * cg[r1];
            }
        }
    }
}

// ---------------------------------------------------------------------------
// Kernel B: channel combination
// ---------------------------------------------------------------------------
__global__ void __launch_bounds__(256)
combine_kernel(const float* __restrict__ comp,
               const float* __restrict__ null_lw, const float* __restrict__ null_iw,
               const float* __restrict__ W_lw, const float* __restrict__ b_lw,
               const float* __restrict__ W_iw, const float* __restrict__ b_iw,
               float* __restrict__ out, int B)
{
    const int b = blockIdx.x * blockDim.x + threadIdx.x;
    if (b >= B) return;

    float tv[NNETS];
    #pragma unroll
    for (int nn = 0; nn < NNETS; ++nn)
        tv[nn] = g_tau[(size_t)nn * B + b];

    float* outG = out;
    float* outL = out + (size_t)30 * B;
    float* outI = out + (size_t)60 * B;

    float ch[30];
    ch[ 0] = tv[ 0] + tv[29] + tv[42] + tv[51] + tv[54] + tv[63];
    ch[ 1] = tv[ 0] + tv[29] + tv[42] + tv[51] + tv[54] + tv[63];
    ch[ 2] = tv[ 1] + tv[30] + tv[43] + tv[52] + tv[55] + tv[64];
    ch[ 3] = tv[ 2] + tv[31] + tv[44] + tv[53] + tv[56] + tv[65];
    ch[ 4] = tv[ 3] + tv[57];
    ch[ 5] = tv[ 4] + tv[58];
    ch[ 6] = tv[ 5] + tv[45];
    ch[ 7] = tv[ 6] + tv[46];
    ch[ 8] = tv[ 7] + tv[59];
    ch[ 9] = tv[ 8] + tv[60];
    ch[10] = tv[ 9] + tv[47];
    ch[11] = tv[10] + tv[48];
    ch[12] = tv[11] + tv[61];
    ch[13] = tv[12] + tv[62];
    ch[14] = tv[13] + tv[49];
    ch[15] = tv[14] + tv[50];
    ch[16] = tv[15] + tv[66];
    ch[17] = tv[16] + tv[67];
    ch[18] = tv[17] + tv[32] + tv[68];
    ch[19] = tv[18] + tv[33] + tv[69];
    ch[20] = tv[19] + tv[34] + tv[70];
    ch[21] = tv[20] + tv[35] + tv[71];
    ch[22] = tv[21] + tv[36] + tv[72];
    ch[23] = tv[22] + tv[37] + tv[73];
    ch[24] = tv[23];
    ch[25] = tv[24];
    ch[26] = tv[25] + tv[38];
    ch[27] = tv[26] + tv[39];
    ch[28] = tv[27] + tv[40] + tv[74];
    ch[29] = tv[28] + tv[41] + tv[75];

    #pragma unroll
    for (int c = 0; c < 30; ++c)
        outG[(size_t)c * B + b] = ch[c];

    const float c6 = comp[(size_t)6 * B + b];
    const float c7 = comp[(size_t)7 * B + b];
    const float nl = null_lw[b];
    const float ni = null_iw[b];
    #pragma unroll
    for (int c = 0; c < 30; ++c) {
        outL[(size_t)c * B + b] = fmaxf(fmaf(nl, W_lw[c], b_lw[c]), 0.0f) * c6;
        outI[(size_t)c * B + b] = fmaxf(fmaf(ni, W_iw[c], b_iw[c]), 0.0f) * c7;
    }
}

// ---------------------------------------------------------------------------
extern "C" void kernel_launch(void* const* d_in, const int* in_sizes, int n_in,
                              void* d_out, int out_size)
{
    const float* t_p     = (const float*)d_in[0];
    const float* comp    = (const float*)d_in[1];
    const float* null_lw = (const float*)d_in[2];
    const float* null_iw = (const float*)d_in[3];
    const float* W1      = (const float*)d_in[4];
    const float* b1      = (const float*)d_in[5];
    const float* W2      = (const float*)d_in[6];
    const float* b2      = (const float*)d_in[7];
    const float* W3      = (const float*)d_in[8];
    const float* b3      = (const float*)d_in[9];
    const float* W_lw    = (const float*)d_in[10];
    const float* b_lw    = (const float*)d_in[11];
    const float* W_iw    = (const float*)d_in[12];
    const float* b_iw    = (const float*)d_in[13];

    const int B = in_sizes[0] / 2;   // t_p is [B, 2]

    mlp_mma_kernel<<<296, 128>>>(t_p, comp, W1, b1, W2, b2, W3, b3, B);

    combine_kernel<<<(B + 255) / 256, 256>>>(comp, null_lw, null_iw,
                                             W_lw, b_lw, W_iw, b_iw,
                                             (float*)d_out, B);
}

// round 6
// speedup vs baseline: 2.3021x; 1.2629x over previous
#include <cuda_runtime.h>
#include <cuda_fp16.h>
#include <cstdint>

#define NNETS 76
#define HD    64

__device__ float g_tau[NNETS * 32768];

// ---------------- helpers ----------------
__device__ __forceinline__ unsigned smem_u32(const void* p) {
    unsigned r;
    asm("{ .reg .u64 t; cvta.to.shared.u64 t, %1; cvt.u32.u64 %0, t; }" : "=r"(r) : "l"(p));
    return r;
}
__device__ __forceinline__ unsigned h2u(__half2 h) {
    return *reinterpret_cast<unsigned*>(&h);
}

#define LDSM4(r0, r1, r2, r3, addr)                                           \
    asm volatile("ldmatrix.sync.aligned.m8n8.x4.shared.b16 {%0,%1,%2,%3}, [%4];" \
                 : "=r"(r0), "=r"(r1), "=r"(r2), "=r"(r3) : "r"(addr))

#define MMA(c, a, b0, b1)                                                     \
    asm volatile("mma.sync.aligned.m16n8k16.row.col.f32.f16.f16.f32 "         \
                 "{%0,%1,%2,%3},{%4,%5,%6,%7},{%8,%9},{%0,%1,%2,%3};"         \
                 : "+f"((c)[0]), "+f"((c)[1]), "+f"((c)[2]), "+f"((c)[3])     \
                 : "r"((a)[0]), "r"((a)[1]), "r"((a)[2]), "r"((a)[3]),        \
                   "r"(b0), "r"(b1))

// ---------------------------------------------------------------------------
// MLP kernel: persistent CTAs over flattened (net, 128-row-tile) job list.
// 128 threads = 4 warps; each warp owns 32 rows of the tile.
// fp16 split-precision: A = hi+lo (2 passes), B = hi only.
// ---------------------------------------------------------------------------
__global__ void __launch_bounds__(128, 3)
mlp_mma_kernel(const float* __restrict__ t_p, const float* __restrict__ comp,
               const float* __restrict__ W1, const float* __restrict__ b1,
               const float* __restrict__ W2, const float* __restrict__ b2,
               const float* __restrict__ W3, const float* __restrict__ b3,
               int B)
{
    __shared__ __align__(128) unsigned char sW2hi[HD * 128];  // [j][k] fp16, swizzled
    __shared__ __align__(8) float sW1a[HD], sW1b[HD], sB1[HD], sB2[HD], sW3[HD];
    __shared__ float sB3;

    const int tid = threadIdx.x;
    const int w   = tid >> 5;
    const int l   = tid & 31;
    const int g   = l >> 2;     // group id (row within 8)
    const int tig = l & 3;      // thread-in-group

    const unsigned w2hi_u = smem_u32(sW2hi);

    const int TPN = B >> 7;                       // tiles per net
    const long long J = (long long)NNETS * TPN;   // total jobs
    const int C  = gridDim.x;
    const int js = (int)((J * blockIdx.x) / C);
    const int je = (int)((J * (blockIdx.x + 1)) / C);

    int curnet = -1;
    const float* cg = nullptr;
    float* taun = nullptr;
    float b3v = 0.f;

    #pragma unroll 1
    for (int job = js; job < je; ++job) {
        const int net  = job / TPN;
        const int tile = job - net * TPN;

        if (net != curnet) {
            __syncthreads();   // all warps done reading previous net's weights
            const float* W2n = W2 + (size_t)net * HD * HD;   // [k][j]
            for (int i = tid; i < HD * HD; i += 128) {
                int k = i >> 6, j = i & 63;
                unsigned off = (unsigned)(j * 128) + ((((unsigned)(k >> 3)) ^ (j & 7)) << 4)
                             + ((k & 7) << 1);
                *(__half*)(sW2hi + off) = __float2half_rn(W2n[i]);
            }
            const float* W1n = W1 + (size_t)net * 2 * HD;
            if (tid < HD) {
                sW1a[tid] = W1n[tid];
                sW1b[tid] = W1n[HD + tid];
                sB1[tid]  = b1[(size_t)net * HD + tid];
                sB2[tid]  = b2[(size_t)net * HD + tid];
                sW3[tid]  = W3[(size_t)net * HD + tid];
            }
            if (tid == 0) sB3 = b3[net];
            __syncthreads();
            curnet = net;
            const int gi = (net < 29) ? 0 : (net < 42) ? 1 : (net < 51) ? 2
                         : (net < 54) ? 3 : (net < 63) ? 4 : 5;
            cg   = comp + (size_t)gi * B;
            taun = g_tau + (size_t)net * B;
            b3v  = sB3;
        }

        const int tbase = tile * 128;
        const int rloc0 = 32 * w + g;   // local rows: rloc0, +8, +16, +24

        // t_p for my 4 fragment rows
        float2 tp[4];
        #pragma unroll
        for (int i = 0; i < 4; ++i)
            tp[i] = ((const float2*)t_p)[tbase + rloc0 + 8 * i];

        // accumulators init with b2 (c0/c2 at col j0, c1/c3 at col j0+1)
        float acc[2][8][4];
        #pragma unroll
        for (int nb = 0; nb < 8; ++nb) {
            float2 b2v = *(const float2*)&sB2[8 * nb + 2 * tig];
            #pragma unroll
            for (int mb = 0; mb < 2; ++mb) {
                acc[mb][nb][0] = b2v.x; acc[mb][nb][1] = b2v.y;
                acc[mb][nb][2] = b2v.x; acc[mb][nb][3] = b2v.y;
            }
        }

        #pragma unroll 1
        for (int kb = 0; kb < 4; ++kb) {
            // ---- layer 1: my A-fragment elements for this k-block ----
            const int k0 = 16 * kb + 2 * tig;        // and k0+8
            const float2 wa0 = *(const float2*)&sW1a[k0];
            const float2 wa1 = *(const float2*)&sW1a[k0 + 8];
            const float2 wb0 = *(const float2*)&sW1b[k0];
            const float2 wb1 = *(const float2*)&sW1b[k0 + 8];
            const float2 bb0 = *(const float2*)&sB1[k0];
            const float2 bb1 = *(const float2*)&sB1[k0 + 8];

            unsigned Ahi[2][4], Alo[2][4];
            #pragma unroll
            for (int i = 0; i < 4; ++i) {
                const float tx = tp[i].x, ty = tp[i].y;
                float h00 = fmaxf(fmaf(tx, wa0.x, fmaf(ty, wb0.x, bb0.x)), 0.f);
                float h01 = fmaxf(fmaf(tx, wa0.y, fmaf(ty, wb0.y, bb0.y)), 0.f);
                float h10 = fmaxf(fmaf(tx, wa1.x, fmaf(ty, wb1.x, bb1.x)), 0.f);
                float h11 = fmaxf(fmaf(tx, wa1.y, fmaf(ty, wb1.y, bb1.y)), 0.f);
                __half2 hh0 = __floats2half2_rn(h00, h01);
                __half2 hh1 = __floats2half2_rn(h10, h11);
                float2 r0 = __half22float2(hh0);
                float2 r1 = __half22float2(hh1);
                __half2 ll0 = __floats2half2_rn(h00 - r0.x, h01 - r0.y);
                __half2 ll1 = __floats2half2_rn(h10 - r1.x, h11 - r1.y);
                const int mb = i >> 1, sl = i & 1;
                Ahi[mb][sl]     = h2u(hh0);
                Ahi[mb][2 + sl] = h2u(hh1);
                Alo[mb][sl]     = h2u(ll0);
                Alo[mb][2 + sl] = h2u(ll1);
            }

            // ---- B fragments + mma (2 precision passes) ----
            const unsigned csel = 2 * kb + (l >> 4);
            #pragma unroll
            for (int np = 0; np < 4; ++np) {
                const unsigned n16 = 16 * np + (((unsigned)(l >> 3) & 1) << 3) + (l & 7);
                const unsigned off = n16 * 128 + ((csel ^ (n16 & 7)) << 4);
                unsigned bh0, bh1, bh2, bh3;
                LDSM4(bh0, bh1, bh2, bh3, w2hi_u + off);
                #pragma unroll
                for (int mb = 0; mb < 2; ++mb) {
                    MMA(acc[mb][2 * np],     Ahi[mb], bh0, bh2);
                    MMA(acc[mb][2 * np],     Alo[mb], bh0, bh2);
                    MMA(acc[mb][2 * np + 1], Ahi[mb], bh1, bh3);
                    MMA(acc[mb][2 * np + 1], Alo[mb], bh1, bh3);
                }
            }
        }

        // ---- epilogue: relu, W3 dot, quad reduce, tau store ----
        #pragma unroll
        for (int mb = 0; mb < 2; ++mb) {
            float p0 = 0.f, p1 = 0.f;
            #pragma unroll
            for (int nb = 0; nb < 8; ++nb) {
                float2 w3v = *(const float2*)&sW3[8 * nb + 2 * tig];
                p0 = fmaf(fmaxf(acc[mb][nb][0], 0.f), w3v.x, p0);
                p0 = fmaf(fmaxf(acc[mb][nb][1], 0.f), w3v.y, p0);
                p1 = fmaf(fmaxf(acc[mb][nb][2], 0.f), w3v.x, p1);
                p1 = fmaf(fmaxf(acc[mb][nb][3], 0.f), w3v.y, p1);
            }
            p0 += __shfl_xor_sync(0xffffffffu, p0, 1);
            p0 += __shfl_xor_sync(0xffffffffu, p0, 2);
            p1 += __shfl_xor_sync(0xffffffffu, p1, 1);
            p1 += __shfl_xor_sync(0xffffffffu, p1, 2);
            if (tig == 0) {
                const int r0 = tbase + 32 * w + 16 * mb + g;
                const int r1 = r0 + 8;
                taun[r0] = fmaxf(p0 + b3v, 0.f) * cg[r0];
                taun[r1] = fmaxf(p1 + b3v, 0.f) * cg[r1];
            }
        }
    }
}

// ---------------------------------------------------------------------------
// Kernel B: channel combination
// ---------------------------------------------------------------------------
__global__ void __launch_bounds__(256)
combine_kernel(const float* __restrict__ comp,
               const float* __restrict__ null_lw, const float* __restrict__ null_iw,
               const float* __restrict__ W_lw, const float* __restrict__ b_lw,
               const float* __restrict__ W_iw, const float* __restrict__ b_iw,
               float* __restrict__ out, int B)
{
    const int b = blockIdx.x * blockDim.x + threadIdx.x;
    if (b >= B) return;

    float tv[NNETS];
    #pragma unroll
    for (int nn = 0; nn < NNETS; ++nn)
        tv[nn] = g_tau[(size_t)nn * B + b];

    float* outG = out;
    float* outL = out + (size_t)30 * B;
    float* outI = out + (size_t)60 * B;

    float ch[30];
    ch[ 0] = tv[ 0] + tv[29] + tv[42] + tv[51] + tv[54] + tv[63];
    ch[ 1] = tv[ 0] + tv[29] + tv[42] + tv[51] + tv[54] + tv[63];
    ch[ 2] = tv[ 1] + tv[30] + tv[43] + tv[52] + tv[55] + tv[64];
    ch[ 3] = tv[ 2] + tv[31] + tv[44] + tv[53] + tv[56] + tv[65];
    ch[ 4] = tv[ 3] + tv[57];
    ch[ 5] = tv[ 4] + tv[58];
    ch[ 6] = tv[ 5] + tv[45];
    ch[ 7] = tv[ 6] + tv[46];
    ch[ 8] = tv[ 7] + tv[59];
    ch[ 9] = tv[ 8] + tv[60];
    ch[10] = tv[ 9] + tv[47];
    ch[11] = tv[10] + tv[48];
    ch[12] = tv[11] + tv[61];
    ch[13] = tv[12] + tv[62];
    ch[14] = tv[13] + tv[49];
    ch[15] = tv[14] + tv[50];
    ch[16] = tv[15] + tv[66];
    ch[17] = tv[16] + tv[67];
    ch[18] = tv[17] + tv[32] + tv[68];
    ch[19] = tv[18] + tv[33] + tv[69];
    ch[20] = tv[19] + tv[34] + tv[70];
    ch[21] = tv[20] + tv[35] + tv[71];
    ch[22] = tv[21] + tv[36] + tv[72];
    ch[23] = tv[22] + tv[37] + tv[73];
    ch[24] = tv[23];
    ch[25] = tv[24];
    ch[26] = tv[25] + tv[38];
    ch[27] = tv[26] + tv[39];
    ch[28] = tv[27] + tv[40] + tv[74];
    ch[29] = tv[28] + tv[41] + tv[75];

    #pragma unroll
    for (int c = 0; c < 30; ++c)
        outG[(size_t)c * B + b] = ch[c];

    const float c6 = comp[(size_t)6 * B + b];
    const float c7 = comp[(size_t)7 * B + b];
    const float nl = null_lw[b];
    const float ni = null_iw[b];
    #pragma unroll
    for (int c = 0; c < 30; ++c) {
        outL[(size_t)c * B + b] = fmaxf(fmaf(nl, W_lw[c], b_lw[c]), 0.0f) * c6;
        outI[(size_t)c * B + b] = fmaxf(fmaf(ni, W_iw[c], b_iw[c]), 0.0f) * c7;
    }
}

// ---------------------------------------------------------------------------
extern "C" void kernel_launch(void* const* d_in, const int* in_sizes, int n_in,
                              void* d_out, int out_size)
{
    const float* t_p     = (const float*)d_in[0];
    const float* comp    = (const float*)d_in[1];
    const float* null_lw = (const float*)d_in[2];
    const float* null_iw = (const float*)d_in[3];
    const float* W1      = (const float*)d_in[4];
    const float* b1      = (const float*)d_in[5];
    const float* W2      = (const float*)d_in[6];
    const float* b2      = (const float*)d_in[7];
    const float* W3      = (const float*)d_in[8];
    const float* b3      = (const float*)d_in[9];
    const float* W_lw    = (const float*)d_in[10];
    const float* b_lw    = (const float*)d_in[11];
    const float* W_iw    = (const float*)d_in[12];
    const float* b_iw    = (const float*)d_in[13];

    const int B = in_sizes[0] / 2;   // t_p is [B, 2]

    mlp_mma_kernel<<<444, 128>>>(t_p, comp, W1, b1, W2, b2, W3, b3, B);

    combine_kernel<<<(B + 255) / 256, 256>>>(comp, null_lw, null_iw,
                                             W_lw, b_lw, W_iw, b_iw,
                                             (float*)d_out, B);
}

// round 7
// speedup vs baseline: 3.6161x; 1.5708x over previous
#include <cuda_runtime.h>
#include <cuda_fp16.h>
#include <cstdint>

#define NNETS 76
#define HD    64

__device__ float g_tau[NNETS * 32768];

// ---------------- helpers ----------------
__device__ __forceinline__ unsigned smem_u32(const void* p) {
    unsigned r;
    asm("{ .reg .u64 t; cvta.to.shared.u64 t, %1; cvt.u32.u64 %0, t; }" : "=r"(r) : "l"(p));
    return r;
}
__device__ __forceinline__ unsigned h2u(__half2 h) {
    return *reinterpret_cast<unsigned*>(&h);
}

#define LDSM4(r0, r1, r2, r3, addr)                                           \
    asm volatile("ldmatrix.sync.aligned.m8n8.x4.shared.b16 {%0,%1,%2,%3}, [%4];" \
                 : "=r"(r0), "=r"(r1), "=r"(r2), "=r"(r3) : "r"(addr))

#define MMA(c, a, b0, b1)                                                     \
    asm volatile("mma.sync.aligned.m16n8k16.row.col.f32.f16.f16.f32 "         \
                 "{%0,%1,%2,%3},{%4,%5,%6,%7},{%8,%9},{%0,%1,%2,%3};"         \
                 : "+f"((c)[0]), "+f"((c)[1]), "+f"((c)[2]), "+f"((c)[3])     \
                 : "r"((a)[0]), "r"((a)[1]), "r"((a)[2]), "r"((a)[3]),        \
                   "r"(b0), "r"(b1))

// ---------------------------------------------------------------------------
// MLP kernel: persistent CTAs over flattened (net, 128-row-tile) job list.
// 128 threads = 4 warps; each warp owns 32 rows of the tile.
// Single-pass fp16 mma (A and B rounded to fp16, f32 accumulate).
// ---------------------------------------------------------------------------
__global__ void __launch_bounds__(128, 3)
mlp_mma_kernel(const float* __restrict__ t_p, const float* __restrict__ comp,
               const float* __restrict__ W1, const float* __restrict__ b1,
               const float* __restrict__ W2, const float* __restrict__ b2,
               const float* __restrict__ W3, const float* __restrict__ b3,
               int B)
{
    __shared__ __align__(128) unsigned char sW2hi[HD * 128];  // [j][k] fp16, swizzled
    __shared__ __align__(8) float sW1a[HD], sW1b[HD], sB1[HD], sB2[HD], sW3[HD];
    __shared__ float sB3;

    const int tid = threadIdx.x;
    const int w   = tid >> 5;
    const int l   = tid & 31;
    const int g   = l >> 2;     // group id (row within 8)
    const int tig = l & 3;      // thread-in-group

    const unsigned w2hi_u = smem_u32(sW2hi);

    const int TPN = B >> 7;                       // tiles per net
    const long long J = (long long)NNETS * TPN;   // total jobs
    const int C  = gridDim.x;
    const int js = (int)((J * blockIdx.x) / C);
    const int je = (int)((J * (blockIdx.x + 1)) / C);

    int curnet = -1;
    const float* cg = nullptr;
    float* taun = nullptr;
    float b3v = 0.f;

    #pragma unroll 1
    for (int job = js; job < je; ++job) {
        const int net  = job / TPN;
        const int tile = job - net * TPN;

        if (net != curnet) {
            __syncthreads();   // all warps done reading previous net's weights
            const float* W2n = W2 + (size_t)net * HD * HD;   // [k][j]
            for (int i = tid; i < HD * HD; i += 128) {
                int k = i >> 6, j = i & 63;
                unsigned off = (unsigned)(j * 128) + ((((unsigned)(k >> 3)) ^ (j & 7)) << 4)
                             + ((k & 7) << 1);
                *(__half*)(sW2hi + off) = __float2half_rn(W2n[i]);
            }
            const float* W1n = W1 + (size_t)net * 2 * HD;
            if (tid < HD) {
                sW1a[tid] = W1n[tid];
                sW1b[tid] = W1n[HD + tid];
                sB1[tid]  = b1[(size_t)net * HD + tid];
                sB2[tid]  = b2[(size_t)net * HD + tid];
                sW3[tid]  = W3[(size_t)net * HD + tid];
            }
            if (tid == 0) sB3 = b3[net];
            __syncthreads();
            curnet = net;
            const int gi = (net < 29) ? 0 : (net < 42) ? 1 : (net < 51) ? 2
                         : (net < 54) ? 3 : (net < 63) ? 4 : 5;
            cg   = comp + (size_t)gi * B;
            taun = g_tau + (size_t)net * B;
            b3v  = sB3;
        }

        const int tbase = tile * 128;
        const int rloc0 = 32 * w + g;   // local rows: rloc0, +8, +16, +24

        // t_p for my 4 fragment rows
        float2 tp[4];
        #pragma unroll
        for (int i = 0; i < 4; ++i)
            tp[i] = ((const float2*)t_p)[tbase + rloc0 + 8 * i];

        // accumulators init with b2 (c0/c2 at col j0, c1/c3 at col j0+1)
        float acc[2][8][4];
        #pragma unroll
        for (int nb = 0; nb < 8; ++nb) {
            float2 b2v = *(const float2*)&sB2[8 * nb + 2 * tig];
            #pragma unroll
            for (int mb = 0; mb < 2; ++mb) {
                acc[mb][nb][0] = b2v.x; acc[mb][nb][1] = b2v.y;
                acc[mb][nb][2] = b2v.x; acc[mb][nb][3] = b2v.y;
            }
        }

        #pragma unroll 1
        for (int kb = 0; kb < 4; ++kb) {
            // ---- layer 1: my A-fragment elements for this k-block ----
            const int k0 = 16 * kb + 2 * tig;        // and k0+8
            const float2 wa0 = *(const float2*)&sW1a[k0];
            const float2 wa1 = *(const float2*)&sW1a[k0 + 8];
            const float2 wb0 = *(const float2*)&sW1b[k0];
            const float2 wb1 = *(const float2*)&sW1b[k0 + 8];
            const float2 bb0 = *(const float2*)&sB1[k0];
            const float2 bb1 = *(const float2*)&sB1[k0 + 8];

            unsigned Ahi[2][4];
            #pragma unroll
            for (int i = 0; i < 4; ++i) {
                const float tx = tp[i].x, ty = tp[i].y;
                float h00 = fmaxf(fmaf(tx, wa0.x, fmaf(ty, wb0.x, bb0.x)), 0.f);
                float h01 = fmaxf(fmaf(tx, wa0.y, fmaf(ty, wb0.y, bb0.y)), 0.f);
                float h10 = fmaxf(fmaf(tx, wa1.x, fmaf(ty, wb1.x, bb1.x)), 0.f);
                float h11 = fmaxf(fmaf(tx, wa1.y, fmaf(ty, wb1.y, bb1.y)), 0.f);
                __half2 hh0 = __floats2half2_rn(h00, h01);
                __half2 hh1 = __floats2half2_rn(h10, h11);
                const int mb = i >> 1, sl = i & 1;
                Ahi[mb][sl]     = h2u(hh0);
                Ahi[mb][2 + sl] = h2u(hh1);
            }

            // ---- B fragments + mma (single precision pass) ----
            const unsigned csel = 2 * kb + (l >> 4);
            #pragma unroll
            for (int np = 0; np < 4; ++np) {
                const unsigned n16 = 16 * np + (((unsigned)(l >> 3) & 1) << 3) + (l & 7);
                const unsigned off = n16 * 128 + ((csel ^ (n16 & 7)) << 4);
                unsigned bh0, bh1, bh2, bh3;
                LDSM4(bh0, bh1, bh2, bh3, w2hi_u + off);
                #pragma unroll
                for (int mb = 0; mb < 2; ++mb) {
                    MMA(acc[mb][2 * np],     Ahi[mb], bh0, bh2);
                    MMA(acc[mb][2 * np + 1], Ahi[mb], bh1, bh3);
                }
            }
        }

        // ---- epilogue: relu, W3 dot, quad reduce, tau store ----
        #pragma unroll
        for (int mb = 0; mb < 2; ++mb) {
            float p0 = 0.f, p1 = 0.f;
            #pragma unroll
            for (int nb = 0; nb < 8; ++nb) {
                float2 w3v = *(const float2*)&sW3[8 * nb + 2 * tig];
                p0 = fmaf(fmaxf(acc[mb][nb][0], 0.f), w3v.x, p0);
                p0 = fmaf(fmaxf(acc[mb][nb][1], 0.f), w3v.y, p0);
                p1 = fmaf(fmaxf(acc[mb][nb][2], 0.f), w3v.x, p1);
                p1 = fmaf(fmaxf(acc[mb][nb][3], 0.f), w3v.y, p1);
            }
            p0 += __shfl_xor_sync(0xffffffffu, p0, 1);
            p0 += __shfl_xor_sync(0xffffffffu, p0, 2);
            p1 += __shfl_xor_sync(0xffffffffu, p1, 1);
            p1 += __shfl_xor_sync(0xffffffffu, p1, 2);
            if (tig == 0) {
                const int r0 = tbase + 32 * w + 16 * mb + g;
                const int r1 = r0 + 8;
                taun[r0] = fmaxf(p0 + b3v, 0.f) * cg[r0];
                taun[r1] = fmaxf(p1 + b3v, 0.f) * cg[r1];
            }
        }
    }
}

// ---------------------------------------------------------------------------
// Kernel B: channel combination
// ---------------------------------------------------------------------------
__global__ void __launch_bounds__(256)
combine_kernel(const float* __restrict__ comp,
               const float* __restrict__ null_lw, const float* __restrict__ null_iw,
               const float* __restrict__ W_lw, const float* __restrict__ b_lw,
               const float* __restrict__ W_iw, const float* __restrict__ b_iw,
               float* __restrict__ out, int B)
{
    const int b = blockIdx.x * blockDim.x + threadIdx.x;
    if (b >= B) return;

    float tv[NNETS];
    #pragma unroll
    for (int nn = 0; nn < NNETS; ++nn)
        tv[nn] = g_tau[(size_t)nn * B + b];

    float* outG = out;
    float* outL = out + (size_t)30 * B;
    float* outI = out + (size_t)60 * B;

    float ch[30];
    ch[ 0] = tv[ 0] + tv[29] + tv[42] + tv[51] + tv[54] + tv[63];
    ch[ 1] = tv[ 0] + tv[29] + tv[42] + tv[51] + tv[54] + tv[63];
    ch[ 2] = tv[ 1] + tv[30] + tv[43] + tv[52] + tv[55] + tv[64];
    ch[ 3] = tv[ 2] + tv[31] + tv[44] + tv[53] + tv[56] + tv[65];
    ch[ 4] = tv[ 3] + tv[57];
    ch[ 5] = tv[ 4] + tv[58];
    ch[ 6] = tv[ 5] + tv[45];
    ch[ 7] = tv[ 6] + tv[46];
    ch[ 8] = tv[ 7] + tv[59];
    ch[ 9] = tv[ 8] + tv[60];
    ch[10] = tv[ 9] + tv[47];
    ch[11] = tv[10] + tv[48];
    ch[12] = tv[11] + tv[61];
    ch[13] = tv[12] + tv[62];
    ch[14] = tv[13] + tv[49];
    ch[15] = tv[14] + tv[50];
    ch[16] = tv[15] + tv[66];
    ch[17] = tv[16] + tv[67];
    ch[18] = tv[17] + tv[32] + tv[68];
    ch[19] = tv[18] + tv[33] + tv[69];
    ch[20] = tv[19] + tv[34] + tv[70];
    ch[21] = tv[20] + tv[35] + tv[71];
    ch[22] = tv[21] + tv[36] + tv[72];
    ch[23] = tv[22] + tv[37] + tv[73];
    ch[24] = tv[23];
    ch[25] = tv[24];
    ch[26] = tv[25] + tv[38];
    ch[27] = tv[26] + tv[39];
    ch[28] = tv[27] + tv[40] + tv[74];
    ch[29] = tv[28] + tv[41] + tv[75];

    #pragma unroll
    for (int c = 0; c < 30; ++c)
        outG[(size_t)c * B + b] = ch[c];

    const float c6 = comp[(size_t)6 * B + b];
    const float c7 = comp[(size_t)7 * B + b];
    const float nl = null_lw[b];
    const float ni = null_iw[b];
    #pragma unroll
    for (int c = 0; c < 30; ++c) {
        outL[(size_t)c * B + b] = fmaxf(fmaf(nl, W_lw[c], b_lw[c]), 0.0f) * c6;
        outI[(size_t)c * B + b] = fmaxf(fmaf(ni, W_iw[c], b_iw[c]), 0.0f) * c7;
    }
}

// ---------------------------------------------------------------------------
extern "C" void kernel_launch(void* const* d_in, const int* in_sizes, int n_in,
                              void* d_out, int out_size)
{
    const float* t_p     = (const float*)d_in[0];
    const float* comp    = (const float*)d_in[1];
    const float* null_lw = (const float*)d_in[2];
    const float* null_iw = (const float*)d_in[3];
    const float* W1      = (const float*)d_in[4];
    const float* b1      = (const float*)d_in[5];
    const float* W2      = (const float*)d_in[6];
    const float* b2      = (const float*)d_in[7];
    const float* W3      = (const float*)d_in[8];
    const float* b3      = (const float*)d_in[9];
    const float* W_lw    = (const float*)d_in[10];
    const float* b_lw    = (const float*)d_in[11];
    const float* W_iw    = (const float*)d_in[12];
    const float* b_iw    = (const float*)d_in[13];

    const int B = in_sizes[0] / 2;   // t_p is [B, 2]

    mlp_mma_kernel<<<444, 128>>>(t_p, comp, W1, b1, W2, b2, W3, b3, B);

    combine_kernel<<<(B + 255) / 256, 256>>>(comp, null_lw, null_iw,
                                             W_lw, b_lw, W_iw, b_iw,
                                             (float*)d_out, B);
}